// round 1
// baseline (speedup 1.0000x reference)
#include <cuda_runtime.h>

#define BATCH 2
#define NSEQ 4096
#define CDIM 128
#define HEADS 4
#define HD 32
#define C2 256
#define MTOT (BATCH*NSEQ)

// ---------------- scratch (device globals; no allocation allowed) ----------------
__device__ float g_h   [MTOT*CDIM];         // LN1 output
__device__ float g_q   [BATCH*HEADS*NSEQ*HD];
__device__ float g_k   [BATCH*HEADS*NSEQ*HD];
__device__ float g_v   [BATCH*HEADS*NSEQ*HD];
__device__ float g_o   [MTOT*CDIM];         // attention output, [b][n][c]
__device__ float g_xmid[MTOT*CDIM];         // x + attn proj
__device__ float g_h2  [MTOT*CDIM];         // LN2 output
__device__ float g_c1  [MTOT*C2];           // conv1 output, channel-last [b][n][256]
__device__ float g_gate[MTOT*CDIM];         // SimpleGate output [b][n][128]

// ---------------- fast exp (x <= 0), 5-FMA poly on FMA pipe ----------------
__device__ __forceinline__ float fexp(float x) {
    float y = fmaxf(x * 1.4426950408889634f, -120.0f);
    int   i = __float2int_rn(y);
    float f = y - (float)i;
    float r = 0.0013333558f;
    r = fmaf(r, f, 0.0096181291f);
    r = fmaf(r, f, 0.0555041087f);
    r = fmaf(r, f, 0.2402265069f);
    r = fmaf(r, f, 0.6931471806f);
    r = fmaf(r, f, 1.0f);
    return r * __int_as_float((i + 127) << 23);
}

// ---------------- LayerNorm: one block per row of 128 ----------------
// WHICH==0: in = xin (external), out = g_h.  WHICH==1: in = g_xmid, out = g_h2.
template<int WHICH>
__global__ void __launch_bounds__(128) ln_kernel(const float* __restrict__ xin,
                                                 const float* __restrict__ w,
                                                 const float* __restrict__ b) {
    const float* in  = (WHICH == 0) ? xin : g_xmid;
    float*       out = (WHICH == 0) ? g_h : g_h2;
    int row = blockIdx.x;
    int t = threadIdx.x;
    float v = in[row*CDIM + t];

    float s = v;
    #pragma unroll
    for (int o = 16; o; o >>= 1) s += __shfl_xor_sync(0xffffffffu, s, o);
    __shared__ float ws[4];
    if ((t & 31) == 0) ws[t >> 5] = s;
    __syncthreads();
    float mu = (ws[0] + ws[1] + ws[2] + ws[3]) * (1.0f/128.0f);

    float d = v - mu;
    float s2 = d * d;
    #pragma unroll
    for (int o = 16; o; o >>= 1) s2 += __shfl_xor_sync(0xffffffffu, s2, o);
    __shared__ float ws2[4];
    if ((t & 31) == 0) ws2[t >> 5] = s2;
    __syncthreads();
    float var = (ws2[0] + ws2[1] + ws2[2] + ws2[3]) * (1.0f/128.0f);

    out[row*CDIM + t] = d * rsqrtf(var + 1e-5f) * w[t] + b[t];
}

// ---------------- GEMM: out[m,o] = sum_k A[m,k] * W[o,k]  (K=128) ----------------
// MODE 0: QKV  (A=g_h,   W0=q_w, W1=kv_w, scatter to g_q/g_k/g_v in [b][h][n][d])
// MODE 1: PROJ (A=g_o,   W0=proj_w, +bias +resid(x ext) -> g_xmid)
// MODE 2: CONV1(A=g_h2,  W0=conv1_w, +bias -> g_c1 [m][256])
// MODE 3: CONV4(A=g_gate,W0=conv4_w, +bias +resid(g_xmid) -> out_ext)
template<int MODE>
__global__ void __launch_bounds__(256) gemm128(const float* __restrict__ W0,
                                               const float* __restrict__ W1,
                                               const float* __restrict__ bias,
                                               const float* __restrict__ resid_ext,
                                               float* __restrict__ out_ext) {
    const float* A;
    if (MODE == 0)      A = g_h;
    else if (MODE == 1) A = g_o;
    else if (MODE == 2) A = g_h2;
    else                A = g_gate;

    __shared__ float As[64][68];   // [k][m-row], padded
    __shared__ float Ws[64][68];   // [k][o-col], padded

    const int tx = threadIdx.x, ty = threadIdx.y;
    const int tid = ty*16 + tx;
    const int m0 = blockIdx.x * 64;
    const int o0 = blockIdx.y * 64;
    const int kk = (tid & 15) * 4;
    const int rw = tid >> 4;

    float acc[4][4] = {};

    #pragma unroll
    for (int kt = 0; kt < 2; ++kt) {
        const int k0 = kt * 64;
        #pragma unroll
        for (int r = 0; r < 4; ++r) {
            const int row = rw + r*16;
            float4 av = *(const float4*)(A + (size_t)(m0 + row)*CDIM + k0 + kk);
            As[kk+0][row] = av.x; As[kk+1][row] = av.y;
            As[kk+2][row] = av.z; As[kk+3][row] = av.w;

            const int o = o0 + row;
            const float* wr;
            if (MODE == 0) wr = (o < CDIM) ? (W0 + (size_t)o*CDIM)
                                           : (W1 + (size_t)(o - CDIM)*CDIM);
            else           wr = W0 + (size_t)o*CDIM;
            float4 wv = *(const float4*)(wr + k0 + kk);
            Ws[kk+0][row] = wv.x; Ws[kk+1][row] = wv.y;
            Ws[kk+2][row] = wv.z; Ws[kk+3][row] = wv.w;
        }
        __syncthreads();
        #pragma unroll
        for (int k = 0; k < 64; ++k) {
            float4 av = *(const float4*)&As[k][ty*4];
            float4 bv = *(const float4*)&Ws[k][tx*4];
            float a[4] = {av.x, av.y, av.z, av.w};
            float b[4] = {bv.x, bv.y, bv.z, bv.w};
            #pragma unroll
            for (int i = 0; i < 4; ++i)
                #pragma unroll
                for (int j = 0; j < 4; ++j)
                    acc[i][j] = fmaf(a[i], b[j], acc[i][j]);
        }
        __syncthreads();
    }

    // ---- epilogue ----
    #pragma unroll
    for (int i = 0; i < 4; ++i) {
        const int m = m0 + ty*4 + i;
        const int obase = o0 + tx*4;
        if (MODE == 0) {
            const int b = m >> 12, n = m & 4095;
            float4 val = make_float4(acc[i][0], acc[i][1], acc[i][2], acc[i][3]);
            if (obase < 128) {
                int o = obase;
                *(float4*)&g_q[(((b*HEADS + (o>>5))*NSEQ + n) << 5) + (o & 31)] = val;
            } else if (obase < 256) {
                int o = obase - 128;
                *(float4*)&g_k[(((b*HEADS + (o>>5))*NSEQ + n) << 5) + (o & 31)] = val;
            } else {
                int o = obase - 256;
                *(float4*)&g_v[(((b*HEADS + (o>>5))*NSEQ + n) << 5) + (o & 31)] = val;
            }
        } else if (MODE == 2) {
            float4 bv = *(const float4*)(bias + obase);
            float4 val = make_float4(acc[i][0]+bv.x, acc[i][1]+bv.y,
                                     acc[i][2]+bv.z, acc[i][3]+bv.w);
            *(float4*)&g_c1[(size_t)m*C2 + obase] = val;
        } else {
            const float* rs = (MODE == 1) ? resid_ext : g_xmid;
            float*       ds = (MODE == 1) ? g_xmid    : out_ext;
            float4 bv = *(const float4*)(bias + obase);
            float4 rv = *(const float4*)(rs + (size_t)m*CDIM + obase);
            float4 val = make_float4(acc[i][0]+bv.x+rv.x, acc[i][1]+bv.y+rv.y,
                                     acc[i][2]+bv.z+rv.z, acc[i][3]+bv.w+rv.w);
            *(float4*)&ds[(size_t)m*CDIM + obase] = val;
        }
    }
}

// ---------------- Flash attention, fp32, thread-per-query-row ----------------
// grid (8 bh, 32 qtiles), block 128. K/V tiles of 32 rows in smem (broadcast reads).
__global__ void __launch_bounds__(128) attn_kernel() {
    const int bh = blockIdx.x;
    const int n  = blockIdx.y * 128 + threadIdx.x;

    const float* Qp = g_q + ((size_t)bh*NSEQ + n)*HD;
    const float* Kp = g_k + (size_t)bh*NSEQ*HD;
    const float* Vp = g_v + (size_t)bh*NSEQ*HD;

    float q[HD];
    #pragma unroll
    for (int d = 0; d < HD; ++d) q[d] = Qp[d] * 0.17677669529663687f;  // 1/sqrt(32)

    float m = -1e30f, l = 0.0f;
    float acc[HD] = {};

    __shared__ float Ks[32][HD];
    __shared__ float Vs[32][HD];

    for (int kt = 0; kt < NSEQ/32; ++kt) {
        const float4* Kg = (const float4*)(Kp + (size_t)kt*32*HD);
        const float4* Vg = (const float4*)(Vp + (size_t)kt*32*HD);
        float4* Ksh = (float4*)&Ks[0][0];
        float4* Vsh = (float4*)&Vs[0][0];
        Ksh[threadIdx.x]       = Kg[threadIdx.x];
        Ksh[threadIdx.x + 128] = Kg[threadIdx.x + 128];
        Vsh[threadIdx.x]       = Vg[threadIdx.x];
        Vsh[threadIdx.x + 128] = Vg[threadIdx.x + 128];
        __syncthreads();

        float s[32];
        #pragma unroll
        for (int j = 0; j < 32; ++j) {
            const float4* kr = (const float4*)&Ks[j][0];
            float t0 = 0, t1 = 0, t2 = 0, t3 = 0;
            #pragma unroll
            for (int d4 = 0; d4 < 8; ++d4) {
                float4 kv = kr[d4];
                t0 = fmaf(q[d4*4+0], kv.x, t0);
                t1 = fmaf(q[d4*4+1], kv.y, t1);
                t2 = fmaf(q[d4*4+2], kv.z, t2);
                t3 = fmaf(q[d4*4+3], kv.w, t3);
            }
            s[j] = (t0 + t1) + (t2 + t3);
        }

        float tm = s[0];
        #pragma unroll
        for (int j = 1; j < 32; ++j) tm = fmaxf(tm, s[j]);
        float mnew = fmaxf(m, tm);
        float corr = fexp(m - mnew);

        l *= corr;
        #pragma unroll
        for (int j = 0; j < 32; ++j) { s[j] = fexp(s[j] - mnew); l += s[j]; }

        #pragma unroll
        for (int d = 0; d < HD; ++d) acc[d] *= corr;
        #pragma unroll
        for (int j = 0; j < 32; ++j) {
            float p = s[j];
            const float4* vr = (const float4*)&Vs[j][0];
            #pragma unroll
            for (int d4 = 0; d4 < 8; ++d4) {
                float4 vv = vr[d4];
                acc[d4*4+0] = fmaf(p, vv.x, acc[d4*4+0]);
                acc[d4*4+1] = fmaf(p, vv.y, acc[d4*4+1]);
                acc[d4*4+2] = fmaf(p, vv.z, acc[d4*4+2]);
                acc[d4*4+3] = fmaf(p, vv.w, acc[d4*4+3]);
            }
        }
        m = mnew;
        __syncthreads();
    }

    const float inv = 1.0f / l;
    const int b = bh >> 2, h = bh & 3;
    float* O = g_o + ((size_t)(b*NSEQ + n))*CDIM + h*HD;
    #pragma unroll
    for (int d = 0; d < HD; ++d) O[d] = acc[d] * inv;
}

// ---------------- fused DW 3x3 + DW 5x5 + sum + SimpleGate ----------------
// Input g_c1 channel-last [b][y][x][256]; output g_gate [b][y][x][128].
__global__ void __launch_bounds__(256) dw_gate_kernel(const float* __restrict__ w33,
                                                      const float* __restrict__ b33,
                                                      const float* __restrict__ w55,
                                                      const float* __restrict__ b55) {
    __shared__ float s33[C2*9];
    __shared__ float s55[C2*25];
    __shared__ float sb[C2];

    const int tid = threadIdx.y*128 + threadIdx.x;
    for (int i = tid; i < C2*9;  i += 256) s33[i] = w33[i];
    for (int i = tid; i < C2*25; i += 256) s55[i] = w55[i];
    if (tid < C2) sb[tid] = b33[tid] + b55[tid];
    __syncthreads();

    const int p = blockIdx.x * 2 + threadIdx.y;      // 0..8191 pixels
    const int b = p >> 12;
    const int n = p & 4095;
    const int y = n >> 6, x = n & 63;
    const int ca = threadIdx.x;
    const int cg = ca + 128;
    const float* base = g_c1 + (size_t)b*NSEQ*C2;

    float acc_a = sb[ca] + base[(size_t)n*C2 + ca];   // identity (x1) term
    float acc_g = sb[cg] + base[(size_t)n*C2 + cg];

    #pragma unroll
    for (int dy = -2; dy <= 2; ++dy) {
        const int yy = y + dy;
        if (yy < 0 || yy > 63) continue;
        #pragma unroll
        for (int dx = -2; dx <= 2; ++dx) {
            const int xx = x + dx;
            if (xx < 0 || xx > 63) continue;
            const float* px = base + (size_t)(yy*64 + xx)*C2;
            const float va = px[ca];
            const float vg = px[cg];
            const int i5 = (dy+2)*5 + (dx+2);
            acc_a = fmaf(va, s55[ca*25 + i5], acc_a);
            acc_g = fmaf(vg, s55[cg*25 + i5], acc_g);
            if (dy >= -1 && dy <= 1 && dx >= -1 && dx <= 1) {
                const int i3 = (dy+1)*3 + (dx+1);
                acc_a = fmaf(va, s33[ca*9 + i3], acc_a);
                acc_g = fmaf(vg, s33[cg*9 + i3], acc_g);
            }
        }
    }
    g_gate[(size_t)(b*NSEQ + n)*CDIM + ca] = acc_a * acc_g;
}

// ---------------- launch ----------------
extern "C" void kernel_launch(void* const* d_in, const int* in_sizes, int n_in,
                              void* d_out, int out_size) {
    (void)in_sizes; (void)n_in; (void)out_size;
    const float* x       = (const float*)d_in[0];
    // d_in[1]=H, d_in[2]=W (int32 scalars) — fixed at 64
    const float* ln1_w   = (const float*)d_in[3];
    const float* ln1_b   = (const float*)d_in[4];
    const float* q_w     = (const float*)d_in[5];
    const float* kv_w    = (const float*)d_in[6];
    const float* proj_w  = (const float*)d_in[7];
    const float* proj_b  = (const float*)d_in[8];
    const float* ln2_w   = (const float*)d_in[9];
    const float* ln2_b   = (const float*)d_in[10];
    const float* conv1_w = (const float*)d_in[11];
    const float* conv1_b = (const float*)d_in[12];
    const float* conv33_w= (const float*)d_in[13];
    const float* conv33_b= (const float*)d_in[14];
    const float* conv55_w= (const float*)d_in[15];
    const float* conv55_b= (const float*)d_in[16];
    const float* conv4_w = (const float*)d_in[17];
    const float* conv4_b = (const float*)d_in[18];
    float* out = (float*)d_out;

    dim3 gthr(16, 16);

    // LN1
    ln_kernel<0><<<MTOT, 128>>>(x, ln1_w, ln1_b);
    // QKV projection (h @ [q_w;kv_w]^T), scatter to per-head layout
    gemm128<0><<<dim3(128, 6), gthr>>>(q_w, kv_w, nullptr, nullptr, nullptr);
    // attention
    attn_kernel<<<dim3(8, 32), 128>>>();
    // proj + bias + residual -> g_xmid
    gemm128<1><<<dim3(128, 2), gthr>>>(proj_w, nullptr, proj_b, x, nullptr);
    // LN2
    ln_kernel<1><<<MTOT, 128>>>(x, ln2_w, ln2_b);
    // conv1 (1x1) -> g_c1 [b][n][256]
    gemm128<2><<<dim3(128, 4), gthr>>>(conv1_w, nullptr, conv1_b, nullptr, nullptr);
    // DW 3x3 + 5x5 + sum + SimpleGate -> g_gate
    dw_gate_kernel<<<4096, dim3(128, 2)>>>(conv33_w, conv33_b, conv55_w, conv55_b);
    // conv4 (1x1) + bias + residual -> out
    gemm128<3><<<dim3(128, 2), gthr>>>(conv4_w, nullptr, conv4_b, nullptr, out);
}